// round 11
// baseline (speedup 1.0000x reference)
#include <cuda_runtime.h>
#include <cuda_bf16.h>

#define D 2048
#define B 16

// Scratch (allocation-free rule: device globals)
__device__ float g_u[B * D];
__device__ float g_diag[B * D];

__device__ __forceinline__ float sigmoidf(float x) {
    return 1.0f / (1.0f + __expf(-x));
}

__device__ __forceinline__ void finalize_one(
    int b, int i, float dA, float dX,
    const float* __restrict__ xt, const float* __restrict__ h,
    const float* __restrict__ ba, const float* __restrict__ bx,
    const float* __restrict__ Lam)
{
    float rt = sigmoidf(dA + __ldg(ba + i));
    float it = sigmoidf(dX + __ldg(bx + i));
    float la = -log1pf(__expf(-__ldg(Lam + i)));   // -softplus(-Lam)
    float t  = la * rt * 0.125f;                   // /C, C=8
    float a  = __expf(t);
    float om = -expm1f(2.0f * t);                  // 1 - a^2, cancellation-free
    float u  = sqrtf(fmaxf(om, 0.0f)) * it * __ldg(xt + b * D + i);
    g_u[b * D + i]    = u;
    g_diag[b * D + i] = a * __ldg(h + b * D + i);
}

// Split float2 -> (bf16x2 hi, bf16x2 lo residual), packed .b32 each.
__device__ __forceinline__ void cvt_split(float2 w, unsigned& hi, unsigned& lo) {
    __nv_bfloat162 h = __float22bfloat162_rn(w);
    float2 hf = __bfloat1622float2(h);
    float2 r  = make_float2(w.x - hf.x, w.y - hf.y);
    __nv_bfloat162 l = __float22bfloat162_rn(r);
    hi = *reinterpret_cast<unsigned*>(&h);
    lo = *reinterpret_cast<unsigned*>(&l);
}

// D(16x8,f32) += A(16x16,bf16,row) * B(16x8,bf16,col)
__device__ __forceinline__ void mma_bf16(float (&d)[4], const unsigned (&a)[4],
                                         unsigned b0, unsigned b1) {
    asm volatile(
        "mma.sync.aligned.m16n8k16.row.col.f32.bf16.bf16.f32 "
        "{%0,%1,%2,%3}, {%4,%5,%6,%7}, {%8,%9}, {%0,%1,%2,%3};\n"
        : "+f"(d[0]), "+f"(d[1]), "+f"(d[2]), "+f"(d[3])
        : "r"(a[0]), "r"(a[1]), "r"(a[2]), "r"(a[3]), "r"(b0), "r"(b1));
}

// Gates on tensor cores (bf16 3-split):
//   Block = 256 threads (8 warps), owns 8 columns n0 = blockIdx.x*8 of BOTH
//   matrices. K=2048 in 8 chunks of 256; within a chunk warp w takes
//   k in [32w, 32w+32) = two m16n8k16 steps. dot = hi*hi + hi*lo + lo*hi.
//   Grid: 256 blocks (one wave at 2 blocks/SM).
#define XPAD 132   // words per staged x row (264 bf16): conflict-free frag loads
__global__ __launch_bounds__(256, 2) void gates_kernel(
    const float* __restrict__ xt, const float* __restrict__ h,
    const float* __restrict__ Wa, const float* __restrict__ Wx,
    const float* __restrict__ ba, const float* __restrict__ bx,
    const float* __restrict__ Lam)
{
    __shared__ unsigned xs_hi[B * XPAD];   // 8448 B
    __shared__ unsigned xs_lo[B * XPAD];   // 8448 B
    __shared__ float    rbuf[8 * 256];     // 8192 B

    const int tid  = threadIdx.x;
    const int lane = tid & 31;
    const int warp = tid >> 5;
    const int n0   = blockIdx.x * 8;

    const int q    = lane >> 2;   // quad id: A row / B column
    const int qk   = lane & 3;    // k sub-offset

    const float* waRow = Wa + (size_t)(n0 + q) * D;
    const float* wxRow = Wx + (size_t)(n0 + q) * D;

    float dA[4] = {0.f, 0.f, 0.f, 0.f};
    float dX[4] = {0.f, 0.f, 0.f, 0.f};

    const float4* xt4 = reinterpret_cast<const float4*>(xt);

#pragma unroll 1
    for (int kt = 0; kt < D; kt += 256) {
        __syncthreads();
        // ---- stage x[16][kt..kt+256) as bf16 hi/lo (16 floats/thread) ----
        {
            const int srow = tid >> 4;
            const int ks   = (tid & 15) << 4;
            const float4* sp = xt4 + srow * (D / 4) + ((kt + ks) >> 2);
            const int wb = srow * XPAD + (ks >> 1);
#pragma unroll
            for (int j = 0; j < 4; j++) {
                float4 xv = __ldg(sp + j);
                unsigned h0, l0, h1, l1;
                cvt_split(make_float2(xv.x, xv.y), h0, l0);
                cvt_split(make_float2(xv.z, xv.w), h1, l1);
                // j-th float4 = bf16-pair words 2j (x,y) and 2j+1 (z,w)
                xs_hi[wb + 2 * j]     = h0;
                xs_hi[wb + 2 * j + 1] = h1;
                xs_lo[wb + 2 * j]     = l0;
                xs_lo[wb + 2 * j + 1] = l1;
            }
        }
        __syncthreads();

        const int kb = 32 * warp;          // this warp's k offset in chunk

#pragma unroll
        for (int s = 0; s < 2; s++) {
            const int kl = kb + 16 * s;    // k-step base within chunk
            const int kg = kt + kl;        // global k

            // ---- A fragments from smem (shared across both matrices) ----
            unsigned ahi[4], alo[4];
            {
                const int r0 = q * XPAD;
                const int r1 = (q + 8) * XPAD;
                const int kw = (kl >> 1) + qk;
                ahi[0] = xs_hi[r0 + kw];     ahi[1] = xs_hi[r1 + kw];
                ahi[2] = xs_hi[r0 + kw + 4]; ahi[3] = xs_hi[r1 + kw + 4];
                alo[0] = xs_lo[r0 + kw];     alo[1] = xs_lo[r1 + kw];
                alo[2] = xs_lo[r0 + kw + 4]; alo[3] = xs_lo[r1 + kw + 4];
            }

            // ---- matrix A (Wa) ----
            {
                float2 w01 = __ldg(reinterpret_cast<const float2*>(waRow + kg) + qk);
                float2 w89 = __ldg(reinterpret_cast<const float2*>(waRow + kg + 8) + qk);
                unsigned bh0, bl0, bh1, bl1;
                cvt_split(w01, bh0, bl0);
                cvt_split(w89, bh1, bl1);
                mma_bf16(dA, ahi, bh0, bh1);
                mma_bf16(dA, ahi, bl0, bl1);
                mma_bf16(dA, alo, bh0, bh1);
            }
            // ---- matrix X (Wx) ----
            {
                float2 w01 = __ldg(reinterpret_cast<const float2*>(wxRow + kg) + qk);
                float2 w89 = __ldg(reinterpret_cast<const float2*>(wxRow + kg + 8) + qk);
                unsigned bh0, bl0, bh1, bl1;
                cvt_split(w01, bh0, bl0);
                cvt_split(w89, bh1, bl1);
                mma_bf16(dX, ahi, bh0, bh1);
                mma_bf16(dX, ahi, bl0, bl1);
                mma_bf16(dX, alo, bh0, bh1);
            }
        }
    }

    // ---- cross-warp reduction: idx = mat*128 + batch*8 + col ----
    __syncthreads();
    {
        float* rb = rbuf + warp * 256;
        const int c = qk * 2;
        rb[q * 8 + c]           = dA[0];
        rb[q * 8 + c + 1]       = dA[1];
        rb[(q + 8) * 8 + c]     = dA[2];
        rb[(q + 8) * 8 + c + 1] = dA[3];
        rb[128 + q * 8 + c]           = dX[0];
        rb[128 + q * 8 + c + 1]       = dX[1];
        rb[128 + (q + 8) * 8 + c]     = dX[2];
        rb[128 + (q + 8) * 8 + c + 1] = dX[3];
    }
    __syncthreads();

    if (tid < 128) {
        float sA = 0.f, sX = 0.f;
#pragma unroll
        for (int w = 0; w < 8; w++) {
            sA += rbuf[w * 256 + tid];
            sX += rbuf[w * 256 + 128 + tid];
        }
        const int b = tid >> 3;
        const int i = n0 + (tid & 7);
        finalize_one(b, i, sA, sX, xt, h, ba, bx, Lam);
    }
}

// Writer: ht[b,i,j] = u[b,j] + (i==j)*diag[b,i].
// Block = (batch b, 16 consecutive rows i). u row held in registers
// (2 float4 / thread, 256 threads = 2048 floats). Streaming stores.
__global__ __launch_bounds__(256) void writer_kernel(float* __restrict__ out) {
    const int b   = blockIdx.y;
    const int i0  = blockIdx.x * 16;
    const int tid = threadIdx.x;

    const float4* u4 = reinterpret_cast<const float4*>(g_u + b * D);
    const float4  va = __ldg(u4 + tid);
    const float4  vb = __ldg(u4 + tid + 256);
    const float*  dg = g_diag + b * D;

    float* obase = out + ((size_t)b * D + (size_t)i0) * D;

#pragma unroll 4
    for (int r = 0; r < 16; r++) {
        const int i  = i0 + r;
        const float dv = __ldg(dg + i);
        float4 sa = va, sb = vb;
        const int qq = i >> 2, c = i & 3;
        if (qq == tid) {
            if      (c == 0) sa.x += dv;
            else if (c == 1) sa.y += dv;
            else if (c == 2) sa.z += dv;
            else             sa.w += dv;
        } else if (qq - 256 == tid) {
            if      (c == 0) sb.x += dv;
            else if (c == 1) sb.y += dv;
            else if (c == 2) sb.z += dv;
            else             sb.w += dv;
        }
        float4* orow = reinterpret_cast<float4*>(obase + (size_t)r * D);
        __stcs(orow + tid, sa);
        __stcs(orow + tid + 256, sb);
    }
}

extern "C" void kernel_launch(void* const* d_in, const int* in_sizes, int n_in,
                              void* d_out, int out_size) {
    const float* xt  = (const float*)d_in[0];
    const float* h   = (const float*)d_in[1];
    const float* Wa  = (const float*)d_in[2];
    const float* Wx  = (const float*)d_in[3];
    const float* ba  = (const float*)d_in[4];
    const float* bx  = (const float*)d_in[5];
    const float* Lam = (const float*)d_in[6];

    gates_kernel<<<256, 256>>>(xt, h, Wa, Wx, ba, bx, Lam);

    dim3 grid(D / 16, B);
    writer_kernel<<<grid, 256>>>((float*)d_out);
}

// round 12
// speedup vs baseline: 1.1481x; 1.1481x over previous
#include <cuda_runtime.h>
#include <cuda_bf16.h>

#define D 2048
#define B 16

#define XPAD 1028                  // words per staged x row (conflict-free frags)
#define SMEM_WORDS (2 * B * XPAD + 8 * 512)
#define SMEM_BYTES (SMEM_WORDS * 4)

// Scratch (allocation-free rule: device globals)
__device__ float g_u[B * D];
__device__ float g_diag[B * D];

__device__ __forceinline__ float sigmoidf(float x) {
    return 1.0f / (1.0f + __expf(-x));
}

__device__ __forceinline__ void finalize_one(
    int b, int i, float dA, float dX,
    const float* __restrict__ xt, const float* __restrict__ h,
    const float* __restrict__ ba, const float* __restrict__ bx,
    const float* __restrict__ Lam)
{
    float rt = sigmoidf(dA + __ldg(ba + i));
    float it = sigmoidf(dX + __ldg(bx + i));
    float la = -log1pf(__expf(-__ldg(Lam + i)));   // -softplus(-Lam)
    float t  = la * rt * 0.125f;                   // /C, C=8
    float a  = __expf(t);
    float om = -expm1f(2.0f * t);                  // 1 - a^2, cancellation-free
    float u  = sqrtf(fmaxf(om, 0.0f)) * it * __ldg(xt + b * D + i);
    g_u[b * D + i]    = u;
    g_diag[b * D + i] = a * __ldg(h + b * D + i);
}

// Split float2 -> (bf16x2 hi, bf16x2 lo residual), packed .b32 each.
__device__ __forceinline__ void cvt_split(float2 w, unsigned& hi, unsigned& lo) {
    __nv_bfloat162 h = __float22bfloat162_rn(w);
    float2 hf = __bfloat1622float2(h);
    float2 r  = make_float2(w.x - hf.x, w.y - hf.y);
    __nv_bfloat162 l = __float22bfloat162_rn(r);
    hi = *reinterpret_cast<unsigned*>(&h);
    lo = *reinterpret_cast<unsigned*>(&l);
}

// D(16x8,f32) += A(16x16,bf16,row) * B(16x8,bf16,col)
__device__ __forceinline__ void mma_bf16(float (&d)[4], const unsigned (&a)[4],
                                         unsigned b0, unsigned b1) {
    asm volatile(
        "mma.sync.aligned.m16n8k16.row.col.f32.bf16.bf16.f32 "
        "{%0,%1,%2,%3}, {%4,%5,%6,%7}, {%8,%9}, {%0,%1,%2,%3};\n"
        : "+f"(d[0]), "+f"(d[1]), "+f"(d[2]), "+f"(d[3])
        : "r"(a[0]), "r"(a[1]), "r"(a[2]), "r"(a[3]), "r"(b0), "r"(b1));
}

// Per-matrix, per-column-group k-step body: load weight pair, split, 3 mmas.
__device__ __forceinline__ void step_mat(
    float (&d)[4], const unsigned (&ahi)[4], const unsigned (&alo)[4],
    const float* wRow, int kg, int qk)
{
    float2 w01 = __ldg(reinterpret_cast<const float2*>(wRow + kg) + qk);
    float2 w89 = __ldg(reinterpret_cast<const float2*>(wRow + kg + 8) + qk);
    unsigned bh0, bl0, bh1, bl1;
    cvt_split(w01, bh0, bl0);
    cvt_split(w89, bh1, bl1);
    mma_bf16(d, ahi, bh0, bh1);
    mma_bf16(d, ahi, bl0, bl1);
    mma_bf16(d, alo, bh0, bh1);
}

// Gates on tensor cores, full-K staging, sync-free mainloop:
//   Grid 128 blocks (single wave), block = 256 threads (8 warps),
//   owns 16 columns n0 = blockIdx.x*16 of BOTH matrices.
//   x (16 x 2048) staged ONCE as bf16 hi/lo in 128.5 KB smem.
//   Warp w covers K in [256w, 256w+256) = 16 m16n8k16 k-steps.
//   dot = hi*hi + hi*lo + lo*hi (lo*lo dropped, ~2^-18 relative).
__global__ __launch_bounds__(256, 1) void gates_kernel(
    const float* __restrict__ xt, const float* __restrict__ h,
    const float* __restrict__ Wa, const float* __restrict__ Wx,
    const float* __restrict__ ba, const float* __restrict__ bx,
    const float* __restrict__ Lam)
{
    extern __shared__ unsigned smem_raw[];
    unsigned* xs_hi = smem_raw;                    // 16 x 1028 words
    unsigned* xs_lo = smem_raw + B * XPAD;         // 16 x 1028 words
    float*    rbuf  = reinterpret_cast<float*>(smem_raw + 2 * B * XPAD); // 8x512

    const int tid  = threadIdx.x;
    const int lane = tid & 31;
    const int warp = tid >> 5;
    const int n0   = blockIdx.x * 16;

    const int q  = lane >> 2;     // quad id: A row / B column
    const int qk = lane & 3;      // k sub-offset

    // ---- prologue: stage all of x as bf16 hi/lo (coalesced float4) ----
    {
        const float4* xt4 = reinterpret_cast<const float4*>(xt);
#pragma unroll
        for (int e = tid; e < B * (D / 4); e += 256) {
            const int row = e >> 9;          // D/4 = 512 float4 per row
            const int c4  = e & 511;
            float4 xv = __ldg(xt4 + row * (D / 4) + c4);
            unsigned h0, l0, h1, l1;
            cvt_split(make_float2(xv.x, xv.y), h0, l0);
            cvt_split(make_float2(xv.z, xv.w), h1, l1);
            const int wb = row * XPAD + 2 * c4;
            xs_hi[wb]     = h0;
            xs_hi[wb + 1] = h1;
            xs_lo[wb]     = l0;
            xs_lo[wb + 1] = l1;
        }
    }
    __syncthreads();

    // Weight row pointers: group 0 -> col n0+q, group 1 -> col n0+8+q.
    const float* waR0 = Wa + (size_t)(n0 + q) * D;
    const float* waR1 = Wa + (size_t)(n0 + 8 + q) * D;
    const float* wxR0 = Wx + (size_t)(n0 + q) * D;
    const float* wxR1 = Wx + (size_t)(n0 + 8 + q) * D;

    float dA0[4] = {0.f, 0.f, 0.f, 0.f};
    float dA1[4] = {0.f, 0.f, 0.f, 0.f};
    float dX0[4] = {0.f, 0.f, 0.f, 0.f};
    float dX1[4] = {0.f, 0.f, 0.f, 0.f};

    const int kb = 256 * warp;    // this warp's K range: [kb, kb+256)

#pragma unroll 4
    for (int s = 0; s < 16; s++) {
        const int kg = kb + 16 * s;
        const int kw = (kg >> 1) + qk;

        unsigned ahi[4], alo[4];
        {
            const int r0 = q * XPAD;
            const int r1 = (q + 8) * XPAD;
            ahi[0] = xs_hi[r0 + kw];     ahi[1] = xs_hi[r1 + kw];
            ahi[2] = xs_hi[r0 + kw + 4]; ahi[3] = xs_hi[r1 + kw + 4];
            alo[0] = xs_lo[r0 + kw];     alo[1] = xs_lo[r1 + kw];
            alo[2] = xs_lo[r0 + kw + 4]; alo[3] = xs_lo[r1 + kw + 4];
        }

        step_mat(dA0, ahi, alo, waR0, kg, qk);
        step_mat(dA1, ahi, alo, waR1, kg, qk);
        step_mat(dX0, ahi, alo, wxR0, kg, qk);
        step_mat(dX1, ahi, alo, wxR1, kg, qk);
    }

    // ---- cross-warp reduction: rbuf[warp][mat*256 + b*16 + col] ----
    __syncthreads();   // staging no longer needed; rbuf region is separate anyway
    {
        float* rb = rbuf + warp * 512;
        const int c = 2 * qk;
#pragma unroll
        for (int g = 0; g < 2; g++) {
            const float* dA = g ? dA1 : dA0;
            const float* dX = g ? dX1 : dX0;
            const int col = 8 * g + c;
            rb[q * 16 + col]             = dA[0];
            rb[q * 16 + col + 1]         = dA[1];
            rb[(q + 8) * 16 + col]       = dA[2];
            rb[(q + 8) * 16 + col + 1]   = dA[3];
            rb[256 + q * 16 + col]           = dX[0];
            rb[256 + q * 16 + col + 1]       = dX[1];
            rb[256 + (q + 8) * 16 + col]     = dX[2];
            rb[256 + (q + 8) * 16 + col + 1] = dX[3];
        }
    }
    __syncthreads();

    {
        const int b   = tid >> 4;
        const int col = tid & 15;
        float sA = 0.f, sX = 0.f;
#pragma unroll
        for (int w = 0; w < 8; w++) {
            sA += rbuf[w * 512 + b * 16 + col];
            sX += rbuf[w * 512 + 256 + b * 16 + col];
        }
        finalize_one(b, n0 + col, sA, sX, xt, h, ba, bx, Lam);
    }
}

// Writer: ht[b,i,j] = u[b,j] + (i==j)*diag[b,i].
// Block = (batch b, 16 consecutive rows i). u row held in registers
// (2 float4 / thread, 256 threads = 2048 floats). Streaming stores.
__global__ __launch_bounds__(256) void writer_kernel(float* __restrict__ out) {
    const int b   = blockIdx.y;
    const int i0  = blockIdx.x * 16;
    const int tid = threadIdx.x;

    const float4* u4 = reinterpret_cast<const float4*>(g_u + b * D);
    const float4  va = __ldg(u4 + tid);
    const float4  vb = __ldg(u4 + tid + 256);
    const float*  dg = g_diag + b * D;

    float* obase = out + ((size_t)b * D + (size_t)i0) * D;

#pragma unroll 4
    for (int r = 0; r < 16; r++) {
        const int i  = i0 + r;
        const float dv = __ldg(dg + i);
        float4 sa = va, sb = vb;
        const int qq = i >> 2, c = i & 3;
        if (qq == tid) {
            if      (c == 0) sa.x += dv;
            else if (c == 1) sa.y += dv;
            else if (c == 2) sa.z += dv;
            else             sa.w += dv;
        } else if (qq - 256 == tid) {
            if      (c == 0) sb.x += dv;
            else if (c == 1) sb.y += dv;
            else if (c == 2) sb.z += dv;
            else             sb.w += dv;
        }
        float4* orow = reinterpret_cast<float4*>(obase + (size_t)r * D);
        __stcs(orow + tid, sa);
        __stcs(orow + tid + 256, sb);
    }
}

extern "C" void kernel_launch(void* const* d_in, const int* in_sizes, int n_in,
                              void* d_out, int out_size) {
    const float* xt  = (const float*)d_in[0];
    const float* h   = (const float*)d_in[1];
    const float* Wa  = (const float*)d_in[2];
    const float* Wx  = (const float*)d_in[3];
    const float* ba  = (const float*)d_in[4];
    const float* bx  = (const float*)d_in[5];
    const float* Lam = (const float*)d_in[6];

    static bool attr_done = false;
    if (!attr_done) {
        cudaFuncSetAttribute(gates_kernel,
                             cudaFuncAttributeMaxDynamicSharedMemorySize,
                             SMEM_BYTES);
        attr_done = true;
    }

    gates_kernel<<<128, 256, SMEM_BYTES>>>(xt, h, Wa, Wx, ba, bx, Lam);

    dim3 grid(D / 16, B);
    writer_kernel<<<grid, 256>>>((float*)d_out);
}

// round 13
// speedup vs baseline: 1.1487x; 1.0006x over previous
#include <cuda_runtime.h>
#include <cuda_bf16.h>

#define D 2048
#define B 16

#define XPAD 1028                  // words per staged x row (conflict-free frags)
#define SMEM_WORDS (2 * B * XPAD)  // rbuf aliases staging (dead after mainloop)
#define SMEM_BYTES (SMEM_WORDS * 4)

// Scratch (allocation-free rule: device globals)
__device__ float g_u[B * D];
__device__ float g_diag[B * D];

__device__ __forceinline__ float sigmoidf(float x) {
    return 1.0f / (1.0f + __expf(-x));
}

__device__ __forceinline__ void finalize_one(
    int b, int i, float dA, float dX,
    const float* __restrict__ xt, const float* __restrict__ h,
    const float* __restrict__ ba, const float* __restrict__ bx,
    const float* __restrict__ Lam)
{
    float rt = sigmoidf(dA + __ldg(ba + i));
    float it = sigmoidf(dX + __ldg(bx + i));
    float la = -log1pf(__expf(-__ldg(Lam + i)));   // -softplus(-Lam)
    float t  = la * rt * 0.125f;                   // /C, C=8
    float a  = __expf(t);
    float om = -expm1f(2.0f * t);                  // 1 - a^2, cancellation-free
    float u  = sqrtf(fmaxf(om, 0.0f)) * it * __ldg(xt + b * D + i);
    g_u[b * D + i]    = u;
    g_diag[b * D + i] = a * __ldg(h + b * D + i);
}

// Split float2 -> (bf16x2 hi, bf16x2 lo residual), packed .b32 each.
__device__ __forceinline__ void cvt_split(float2 w, unsigned& hi, unsigned& lo) {
    __nv_bfloat162 h = __float22bfloat162_rn(w);
    float2 hf = __bfloat1622float2(h);
    float2 r  = make_float2(w.x - hf.x, w.y - hf.y);
    __nv_bfloat162 l = __float22bfloat162_rn(r);
    hi = *reinterpret_cast<unsigned*>(&h);
    lo = *reinterpret_cast<unsigned*>(&l);
}

// D(16x8,f32) += A(16x16,bf16,row) * B(16x8,bf16,col)
__device__ __forceinline__ void mma_bf16(float (&d)[4], const unsigned (&a)[4],
                                         unsigned b0, unsigned b1) {
    asm volatile(
        "mma.sync.aligned.m16n8k16.row.col.f32.bf16.bf16.f32 "
        "{%0,%1,%2,%3}, {%4,%5,%6,%7}, {%8,%9}, {%0,%1,%2,%3};\n"
        : "+f"(d[0]), "+f"(d[1]), "+f"(d[2]), "+f"(d[3])
        : "r"(a[0]), "r"(a[1]), "r"(a[2]), "r"(a[3]), "r"(b0), "r"(b1));
}

// Per-matrix, per-column-group k-step body: load weight pair, split, 3 mmas.
__device__ __forceinline__ void step_mat(
    float (&d)[4], const unsigned (&ahi)[4], const unsigned (&alo)[4],
    const float* wRow, int kg, int qk)
{
    float2 w01 = __ldg(reinterpret_cast<const float2*>(wRow + kg) + qk);
    float2 w89 = __ldg(reinterpret_cast<const float2*>(wRow + kg + 8) + qk);
    unsigned bh0, bl0, bh1, bl1;
    cvt_split(w01, bh0, bl0);
    cvt_split(w89, bh1, bl1);
    mma_bf16(d, ahi, bh0, bh1);
    mma_bf16(d, ahi, bl0, bl1);
    mma_bf16(d, alo, bh0, bh1);
}

// Gates on tensor cores, full-K staging, sync-free mainloop:
//   Grid 128 blocks (single wave, 1 block/SM), block = 512 threads (16 warps,
//   4 warps/SMSP). Block owns 16 columns n0 = blockIdx.x*16 of BOTH matrices.
//   x (16 x 2048) staged ONCE as bf16 hi/lo in 131.6 KB smem.
//   Warp w covers K in [128w, 128w+128) = 8 m16n8k16 k-steps.
//   dot = hi*hi + hi*lo + lo*hi (lo*lo dropped, ~2^-18 relative).
__global__ __launch_bounds__(512, 1) void gates_kernel(
    const float* __restrict__ xt, const float* __restrict__ h,
    const float* __restrict__ Wa, const float* __restrict__ Wx,
    const float* __restrict__ ba, const float* __restrict__ bx,
    const float* __restrict__ Lam)
{
    extern __shared__ unsigned smem_raw[];
    unsigned* xs_hi = smem_raw;                    // 16 x 1028 words
    unsigned* xs_lo = smem_raw + B * XPAD;         // 16 x 1028 words
    // rbuf aliases staging storage; only used AFTER the post-mainloop sync.
    float*    rbuf  = reinterpret_cast<float*>(smem_raw);   // 16 x 512 floats

    const int tid  = threadIdx.x;
    const int lane = tid & 31;
    const int warp = tid >> 5;
    const int n0   = blockIdx.x * 16;

    const int q  = lane >> 2;     // quad id: A row / B column
    const int qk = lane & 3;      // k sub-offset

    // ---- prologue: stage all of x as bf16 hi/lo (coalesced float4) ----
    {
        const float4* xt4 = reinterpret_cast<const float4*>(xt);
#pragma unroll
        for (int e = tid; e < B * (D / 4); e += 512) {
            const int row = e >> 9;          // D/4 = 512 float4 per row
            const int c4  = e & 511;
            float4 xv = __ldg(xt4 + row * (D / 4) + c4);
            unsigned h0, l0, h1, l1;
            cvt_split(make_float2(xv.x, xv.y), h0, l0);
            cvt_split(make_float2(xv.z, xv.w), h1, l1);
            const int wb = row * XPAD + 2 * c4;
            xs_hi[wb]     = h0;
            xs_hi[wb + 1] = h1;
            xs_lo[wb]     = l0;
            xs_lo[wb + 1] = l1;
        }
    }
    __syncthreads();

    // Weight row pointers: group 0 -> col n0+q, group 1 -> col n0+8+q.
    const float* waR0 = Wa + (size_t)(n0 + q) * D;
    const float* waR1 = Wa + (size_t)(n0 + 8 + q) * D;
    const float* wxR0 = Wx + (size_t)(n0 + q) * D;
    const float* wxR1 = Wx + (size_t)(n0 + 8 + q) * D;

    float dA0[4] = {0.f, 0.f, 0.f, 0.f};
    float dA1[4] = {0.f, 0.f, 0.f, 0.f};
    float dX0[4] = {0.f, 0.f, 0.f, 0.f};
    float dX1[4] = {0.f, 0.f, 0.f, 0.f};

    const int kb = 128 * warp;    // this warp's K range: [kb, kb+128)

#pragma unroll 4
    for (int s = 0; s < 8; s++) {
        const int kg = kb + 16 * s;
        const int kw = (kg >> 1) + qk;

        unsigned ahi[4], alo[4];
        {
            const int r0 = q * XPAD;
            const int r1 = (q + 8) * XPAD;
            ahi[0] = xs_hi[r0 + kw];     ahi[1] = xs_hi[r1 + kw];
            ahi[2] = xs_hi[r0 + kw + 4]; ahi[3] = xs_hi[r1 + kw + 4];
            alo[0] = xs_lo[r0 + kw];     alo[1] = xs_lo[r1 + kw];
            alo[2] = xs_lo[r0 + kw + 4]; alo[3] = xs_lo[r1 + kw + 4];
        }

        step_mat(dA0, ahi, alo, waR0, kg, qk);
        step_mat(dA1, ahi, alo, waR1, kg, qk);
        step_mat(dX0, ahi, alo, wxR0, kg, qk);
        step_mat(dX1, ahi, alo, wxR1, kg, qk);
    }

    // ---- cross-warp reduction: rbuf[warp][mat*256 + b*16 + col] ----
    __syncthreads();   // staging reads complete everywhere; safe to alias rbuf
    {
        float* rb = rbuf + warp * 512;
        const int c = 2 * qk;
#pragma unroll
        for (int g = 0; g < 2; g++) {
            const float* dA = g ? dA1 : dA0;
            const float* dX = g ? dX1 : dX0;
            const int col = 8 * g + c;
            rb[q * 16 + col]             = dA[0];
            rb[q * 16 + col + 1]         = dA[1];
            rb[(q + 8) * 16 + col]       = dA[2];
            rb[(q + 8) * 16 + col + 1]   = dA[3];
            rb[256 + q * 16 + col]           = dX[0];
            rb[256 + q * 16 + col + 1]       = dX[1];
            rb[256 + (q + 8) * 16 + col]     = dX[2];
            rb[256 + (q + 8) * 16 + col + 1] = dX[3];
        }
    }
    __syncthreads();

    if (tid < 256) {
        const int b   = tid >> 4;
        const int col = tid & 15;
        float sA = 0.f, sX = 0.f;
#pragma unroll
        for (int w = 0; w < 16; w++) {
            sA += rbuf[w * 512 + b * 16 + col];
            sX += rbuf[w * 512 + 256 + b * 16 + col];
        }
        finalize_one(b, n0 + col, sA, sX, xt, h, ba, bx, Lam);
    }
}

// Writer: ht[b,i,j] = u[b,j] + (i==j)*diag[b,i].
// Block = (batch b, 16 consecutive rows i). u row held in registers
// (2 float4 / thread, 256 threads = 2048 floats). Streaming stores.
__global__ __launch_bounds__(256) void writer_kernel(float* __restrict__ out) {
    const int b   = blockIdx.y;
    const int i0  = blockIdx.x * 16;
    const int tid = threadIdx.x;

    const float4* u4 = reinterpret_cast<const float4*>(g_u + b * D);
    const float4  va = __ldg(u4 + tid);
    const float4  vb = __ldg(u4 + tid + 256);
    const float*  dg = g_diag + b * D;

    float* obase = out + ((size_t)b * D + (size_t)i0) * D;

#pragma unroll 4
    for (int r = 0; r < 16; r++) {
        const int i  = i0 + r;
        const float dv = __ldg(dg + i);
        float4 sa = va, sb = vb;
        const int qq = i >> 2, c = i & 3;
        if (qq == tid) {
            if      (c == 0) sa.x += dv;
            else if (c == 1) sa.y += dv;
            else if (c == 2) sa.z += dv;
            else             sa.w += dv;
        } else if (qq - 256 == tid) {
            if      (c == 0) sb.x += dv;
            else if (c == 1) sb.y += dv;
            else if (c == 2) sb.z += dv;
            else             sb.w += dv;
        }
        float4* orow = reinterpret_cast<float4*>(obase + (size_t)r * D);
        __stcs(orow + tid, sa);
        __stcs(orow + tid + 256, sb);
    }
}

extern "C" void kernel_launch(void* const* d_in, const int* in_sizes, int n_in,
                              void* d_out, int out_size) {
    const float* xt  = (const float*)d_in[0];
    const float* h   = (const float*)d_in[1];
    const float* Wa  = (const float*)d_in[2];
    const float* Wx  = (const float*)d_in[3];
    const float* ba  = (const float*)d_in[4];
    const float* bx  = (const float*)d_in[5];
    const float* Lam = (const float*)d_in[6];

    static bool attr_done = false;
    if (!attr_done) {
        cudaFuncSetAttribute(gates_kernel,
                             cudaFuncAttributeMaxDynamicSharedMemorySize,
                             SMEM_BYTES);
        attr_done = true;
    }

    gates_kernel<<<128, 512, SMEM_BYTES>>>(xt, h, Wa, Wx, ba, bx, Lam);

    dim3 grid(D / 16, B);
    writer_kernel<<<grid, 256>>>((float*)d_out);
}